// round 12
// baseline (speedup 1.0000x reference)
#include <cuda_runtime.h>
#include <cuda_fp16.h>
#include <cstdint>

#define B_    128
#define T_    25
#define L_    49
#define V_    10000
#define E_    512
#define H_    512
#define ENC_  512
#define BL_   (B_ * L_)      // 6272
#define BT_   (B_ * T_)      // 3200
#define VPAD_ 10112          // 79 * 128

typedef unsigned long long ull;

// ---------------- device scratch ----------------
__device__ float g_enc_proj[BL_ * H_];              // [6272][512]
__device__ float g_gates_pre[(size_t)BT_ * 4 * H_]; // [3200][2048] permuted cols
__device__ float g_bsum[4 * H_];                    // permuted
__device__ float g_big1[B_ * 2560];                 // [128][hp(512)|gates_h(2048)]
__device__ float g_c[2 * B_ * H_];
// fp16 HMMA operands (single-term, row-major [N][512])
__device__ __align__(16) __half g_Wbig[(size_t)VPAD_ * 512];
__device__ __align__(16) __half g_hbig[(size_t)(T_ + 1) * B_ * 512];
__device__ __align__(16) __half g_W1H[2560 * 512];  // [W_h | perm(W_hh)]
__device__ __align__(16) __half g_W2H[2048 * 512];  // perm(W_ih[:,512:])
__device__ __align__(16) __half g_ctxH[B_ * 512];
__device__ __align__(16) __half g_encA[(size_t)BL_ * 512];
__device__ __align__(16) __half g_embX[(size_t)BT_ * 512];
__device__ __align__(16) __half g_WeB[(size_t)H_ * 512];
__device__ __align__(16) __half g_WihB[(size_t)(4 * H_) * 512];

// ---------------- fast transcendentals ----------------
__device__ __forceinline__ float fex2(float x) {
    float y; asm("ex2.approx.ftz.f32 %0, %1;" : "=f"(y) : "f"(x)); return y;
}
__device__ __forceinline__ float frcp(float x) {
    float y; asm("rcp.approx.ftz.f32 %0, %1;" : "=f"(y) : "f"(x)); return y;
}
__device__ __forceinline__ float ftanh_hw(float x) {
    float y; asm("tanh.approx.f32 %0, %1;" : "=f"(y) : "f"(x)); return y;
}
__device__ __forceinline__ float ftanh(float x) {
    float xc = fminf(fmaxf(x, -8.f), 8.f);
    float e = fex2(xc * 2.8853900817779268f);
    return (e - 1.f) * frcp(e + 1.f);
}
__device__ __forceinline__ float fsig(float x) {
    float xc = fminf(fmaxf(x, -30.f), 30.f);
    float e = fex2(-xc * 1.4426950408889634f);
    return frcp(1.f + e);
}

// ---------------- mma.sync helpers ----------------
__device__ __forceinline__ uint32_t smem_u32(const void* p) {
    uint32_t a;
    asm("{ .reg .u64 t; cvta.to.shared.u64 t, %1; cvt.u32.u64 %0, t; }"
        : "=r"(a) : "l"(p));
    return a;
}
__device__ __forceinline__ void ldm_x4(uint32_t* r, uint32_t addr) {
    asm volatile("ldmatrix.sync.aligned.m8n8.x4.shared.b16 {%0,%1,%2,%3}, [%4];"
        : "=r"(r[0]), "=r"(r[1]), "=r"(r[2]), "=r"(r[3]) : "r"(addr));
}
__device__ __forceinline__ void ldm_x2(uint32_t* r, uint32_t addr) {
    asm volatile("ldmatrix.sync.aligned.m8n8.x2.shared.b16 {%0,%1}, [%2];"
        : "=r"(r[0]), "=r"(r[1]) : "r"(addr));
}
__device__ __forceinline__ void mma_f16(float* d, const uint32_t* a,
                                        uint32_t b0, uint32_t b1) {
    asm volatile("mma.sync.aligned.m16n8k16.row.col.f32.f16.f16.f32 "
        "{%0,%1,%2,%3}, {%4,%5,%6,%7}, {%8,%9}, {%0,%1,%2,%3};"
        : "+f"(d[0]), "+f"(d[1]), "+f"(d[2]), "+f"(d[3])
        : "r"(a[0]), "r"(a[1]), "r"(a[2]), "r"(a[3]), "r"(b0), "r"(b1));
}
__device__ __forceinline__ void cp16(uint32_t dst, const void* src) {
    asm volatile("cp.async.cg.shared.global [%0], [%1], 16;"
                 :: "r"(dst), "l"(src));
}

#define KLEN_ 512
#define NCH_  16
#define SMEM128_ (4 * 256 * 80)    // BN=128
#define SMEM64_  (4 * 192 * 80)    // BN=64
#define SMEM32_  (4 * 160 * 80)    // BN=32

// ---------------------------------------------------------------------------
// Templated HMMA mainloop: CTA 128m x BN n, K=512, 8 warps (2m x 4n),
// cp.async 4-stage pipeline. Results in cx.d[4][FN][4], FN = BN/32.
// ---------------------------------------------------------------------------
template<int BN>
struct MmaCtx {
    static constexpr int FN = BN / 32;   // n8 fragments per warp
    float d[4][FN][4];
    int arow, acol, l, wm, wn;
    uint32_t sb;
};

template<int BN>
__device__ __forceinline__ void mma_mainloop(
    MmaCtx<BN>& cx, const __half* Asrc, const __half* Bsrc, __half* smh)
{
    constexpr int FN = BN / 32;
    constexpr int ROWS = 128 + BN;
    constexpr int STAGE = ROWS * 80;
    constexpr int NW = BN / 4;           // n per warp
    const int tid = threadIdx.x;
    const int l = tid & 31, wid = tid >> 5;
    cx.l = l; cx.wm = wid >> 2; cx.wn = wid & 3;
    cx.sb = smem_u32(smh);
#pragma unroll
    for (int i = 0; i < 4; i++)
#pragma unroll
        for (int j = 0; j < FN; j++)
#pragma unroll
            for (int q = 0; q < 4; q++) cx.d[i][j][q] = 0.f;

    cx.arow = cx.wm * 64 + (l & 15);
    cx.acol = (l >> 4) * 8;
    const int brow4 = cx.wn * NW + ((l >> 4) << 3) + (l & 7);  // x4 path
    const int bcol4 = ((l >> 3) & 1) * 8;
    const int brow2 = cx.wn * NW + (l & 7);                    // x2 path
    const int bcol2 = ((l >> 3) & 1) * 8;

    const int lr = tid >> 2;
    const int lc = (tid & 3) * 8;

    auto issue_chunk = [&](int c, int buf) {
        const uint32_t dbase = cx.sb + buf * STAGE;
#pragma unroll
        for (int q = 0; q < (ROWS * 4 + 255) / 256; q++) {
            int idx = tid + q * 256;
            if (ROWS % 64 != 0 && idx >= ROWS * 4) break;
            int r = idx >> 2;
            int cc = (idx & 3) * 8;
            const __half* s = (r < 128) ? (Asrc + (size_t)r * KLEN_)
                                        : (Bsrc + (size_t)(r - 128) * KLEN_);
            cp16(dbase + r * 80 + cc * 2, s + c * 32 + cc);
        }
        asm volatile("cp.async.commit_group;" ::: "memory");
    };

    issue_chunk(0, 0);
    issue_chunk(1, 1);
    issue_chunk(2, 2);

#pragma unroll 1
    for (int c = 0; c < NCH_; c++) {
        if (c + 3 < NCH_) asm volatile("cp.async.wait_group 2;" ::: "memory");
        else              asm volatile("cp.async.wait_group 0;" ::: "memory");
        __syncthreads();
        if (c + 3 < NCH_) issue_chunk(c + 3, (c + 3) & 3);
        const uint32_t base = cx.sb + (c & 3) * STAGE;
#pragma unroll
        for (int s = 0; s < 2; s++) {
            uint32_t ar[4][4];
#pragma unroll
            for (int fm = 0; fm < 4; fm++)
                ldm_x4(ar[fm],
                       base + ((cx.arow + fm * 16) * 40 + cx.acol + s * 16) * 2);
            uint32_t br[2 * FN];
            if (FN == 1) {
                ldm_x2(br, base + 128 * 80 +
                           ((brow2) * 40 + bcol2 + s * 16) * 2);
            } else {
#pragma unroll
                for (int fp = 0; fp < FN / 2; fp++)
                    ldm_x4(br + 4 * fp, base + 128 * 80 +
                           ((brow4 + fp * 16) * 40 + bcol4 + s * 16) * 2);
            }
#pragma unroll
            for (int fn = 0; fn < FN; fn++)
#pragma unroll
                for (int fm = 0; fm < 4; fm++)
                    mma_f16(cx.d[fm][fn], ar[fm], br[2 * fn], br[2 * fn + 1]);
        }
    }
}

// ---------------------------------------------------------------------------
// Generic GEMM (fp32 out, optional bias). grid(N/BN, M/128).
// ---------------------------------------------------------------------------
template<int BN>
__global__ void __launch_bounds__(256) mma_gemm(
    const __half* __restrict__ A, const __half* __restrict__ Bm,
    const float* __restrict__ bias, float* __restrict__ out,
    long ldout, int Nvalid)
{
    extern __shared__ __align__(16) __half smh[];
    const int mbase = blockIdx.y * 128;
    const int nbase = blockIdx.x * BN;
    MmaCtx<BN> cx;
    mma_mainloop<BN>(cx, A + (size_t)mbase * KLEN_,
                     Bm + (size_t)nbase * KLEN_, smh);

#pragma unroll
    for (int fm = 0; fm < 4; fm++) {
        int m0 = mbase + cx.wm * 64 + fm * 16 + (cx.l >> 2);
#pragma unroll
        for (int fn = 0; fn < MmaCtx<BN>::FN; fn++) {
            int n0 = nbase + cx.wn * (BN / 4) + fn * 8 + (cx.l & 3) * 2;
            if (n0 < Nvalid) {
                float b0 = bias ? bias[n0] : 0.f;
                float b1 = bias ? bias[n0 + 1] : 0.f;
                float2 v0 = make_float2(cx.d[fm][fn][0] + b0, cx.d[fm][fn][1] + b1);
                float2 v1 = make_float2(cx.d[fm][fn][2] + b0, cx.d[fm][fn][3] + b1);
                *(float2*)&out[(size_t)m0 * ldout + n0] = v0;
                *(float2*)&out[(size_t)(m0 + 8) * ldout + n0] = v1;
            }
        }
    }
}

// ---------------------------------------------------------------------------
// gemm2 + LSTM pointwise fused (BN=32): gates tile = ctx@W2^T + big1_gh +
// gates_pre, then c/h update.  grid(64): nbase = bx*32 gate-cols.
// ---------------------------------------------------------------------------
__global__ void __launch_bounds__(256) gemm2_lstm(int t) {
    extern __shared__ __align__(16) __half smh[];
    const int nbase = blockIdx.x * 32;
    MmaCtx<32> cx;
    mma_mainloop<32>(cx, g_ctxH, g_W2H + (size_t)nbase * KLEN_, smh);

    __syncthreads();                        // pipeline smem -> gates smem reuse
    float* gsm = reinterpret_cast<float*>(smh);   // [128][33]
#pragma unroll
    for (int fm = 0; fm < 4; fm++) {
        int m0 = cx.wm * 64 + fm * 16 + (cx.l >> 2);
        int n0 = cx.wn * 8 + (cx.l & 3) * 2;
#pragma unroll
        for (int hh = 0; hh < 2; hh++) {
            int m = m0 + hh * 8;
            const float* pre =
                &g_gates_pre[((size_t)(t * B_ + m)) * 2048 + nbase + n0];
            const float* bh = &g_big1[m * 2560 + 512 + nbase + n0];
            gsm[m * 33 + n0]     = cx.d[fm][0][hh * 2]     + bh[0] + pre[0];
            gsm[m * 33 + n0 + 1] = cx.d[fm][0][hh * 2 + 1] + bh[1] + pre[1];
        }
    }
    __syncthreads();

    const int tid = threadIdx.x;
#pragma unroll
    for (int q = 0; q < 4; q++) {
        int idx = tid + q * 256;
        int b = idx >> 3, ul = idx & 7;     // 128 b x 8 units
        int u = (nbase >> 2) + ul;
        float gi = gsm[b * 33 + ul * 4 + 0];
        float gf = gsm[b * 33 + ul * 4 + 1];
        float gg = gsm[b * 33 + ul * 4 + 2];
        float go = gsm[b * 33 + ul * 4 + 3];
        float cn = fsig(gf) * g_c[(size_t)(t & 1) * (B_ * H_) + b * H_ + u]
                 + fsig(gi) * ftanh(gg);
        g_c[(size_t)((t + 1) & 1) * (B_ * H_) + b * H_ + u] = cn;
        float h = fsig(go) * ftanh(cn);
        g_hbig[(size_t)(t + 1) * (B_ * 512) + b * 512 + u] = __float2half_rn(h);
    }
}

// ---------------------------------------------------------------------------
// Attention: hp from big1[:, 0:512]; scores; softmax; ctx -> ctxH fp16.
// ---------------------------------------------------------------------------
__global__ void __launch_bounds__(512) attn_kernel(
    const float* __restrict__ enc, const float* __restrict__ vattn) {
    const int b = blockIdx.x, tid = threadIdx.x;
    __shared__ float hp_s[H_];
    __shared__ float v_s[H_];
    __shared__ float sc[64];

    hp_s[tid] = g_big1[b * 2560 + tid];
    v_s[tid] = vattn[tid];
    __syncthreads();

    const int w = tid >> 5, lane = tid & 31;
    const float* ep = g_enc_proj + (size_t)b * L_ * H_;
    for (int l = w; l < L_; l += 16) {
        const float* row = ep + l * H_;
        float p = 0.f;
#pragma unroll
        for (int k = lane; k < H_; k += 32)
            p += ftanh_hw(hp_s[k] + row[k]) * v_s[k];
#pragma unroll
        for (int o = 16; o; o >>= 1) p += __shfl_xor_sync(0xffffffffu, p, o);
        if (lane == 0) sc[l] = p;
    }
    __syncthreads();

    if (tid < 32) {
        float v0 = sc[tid];
        float v1 = (tid < L_ - 32) ? sc[32 + tid] : -1e30f;
        float mx = fmaxf(v0, v1);
#pragma unroll
        for (int o = 16; o; o >>= 1) mx = fmaxf(mx, __shfl_xor_sync(0xffffffffu, mx, o));
        float e0 = fex2((v0 - mx) * 1.4426950408889634f);
        float e1 = (tid < L_ - 32) ? fex2((v1 - mx) * 1.4426950408889634f) : 0.f;
        float s = e0 + e1;
#pragma unroll
        for (int o = 16; o; o >>= 1) s += __shfl_xor_sync(0xffffffffu, s, o);
        float r = frcp(s);
        sc[tid] = e0 * r;
        if (tid < L_ - 32) sc[32 + tid] = e1 * r;
    }
    __syncthreads();

    const float* eb = enc + (size_t)b * L_ * ENC_;
    float a = 0.f;
#pragma unroll 7
    for (int l = 0; l < L_; l++) a += sc[l] * eb[l * ENC_ + tid];
    g_ctxH[b * 512 + tid] = __float2half_rn(a);
}

// ---------------------------------------------------------------------------
// preamble kernels (fp16 converts)
// ---------------------------------------------------------------------------
__global__ void bias_sum_perm(const float* __restrict__ bi,
                              const float* __restrict__ bh) {
    int n = blockIdx.x * 256 + threadIdx.x;
    int o = ((n & 3) << 9) | (n >> 2);
    g_bsum[n] = bi[o] + bh[o];
}

__global__ void wfc_conv(const float* __restrict__ W_fc) {
    int n = blockIdx.x, j = threadIdx.x;
    float w = (n < V_) ? W_fc[(size_t)n * H_ + j] : 0.f;
    g_Wbig[(size_t)n * 512 + j] = __float2half_rn(w);
}

__global__ void w1h_conv(const float* __restrict__ W_h,
                         const float* __restrict__ W_hh) {
    int n = blockIdx.x, j = threadIdx.x;
    float w;
    if (n < 512) w = W_h[(size_t)n * H_ + j];
    else {
        int p = n - 512;
        int o = ((p & 3) << 9) | (p >> 2);
        w = W_hh[(size_t)o * H_ + j];
    }
    g_W1H[(size_t)n * 512 + j] = __float2half_rn(w);
}

__global__ void w2_conv(const float* __restrict__ W_ih) {
    int n = blockIdx.x, j = threadIdx.x;
    int o = ((n & 3) << 9) | (n >> 2);
    g_W2H[(size_t)n * 512 + j] = __float2half_rn(W_ih[(size_t)o * 1024 + 512 + j]);
}

__global__ void wih_emb_conv(const float* __restrict__ W_ih) {
    int n = blockIdx.x, j = threadIdx.x;
    int o = ((n & 3) << 9) | (n >> 2);
    g_WihB[(size_t)n * 512 + j] = __float2half_rn(W_ih[(size_t)o * 1024 + j]);
}

__global__ void h16_conv(const float* __restrict__ src, __half* __restrict__ dst) {
    int m = blockIdx.x, j = threadIdx.x;
    dst[(size_t)m * 512 + j] = __float2half_rn(src[(size_t)m * 512 + j]);
}

__global__ void emb_gather(const int* __restrict__ cap, const float* __restrict__ emb) {
    int m = blockIdx.x;
    int b = m & 127, t = m >> 7;
    int w = cap[b * T_ + t];
    int j = threadIdx.x;
    g_embX[(size_t)m * 512 + j] = __float2half_rn(emb[(size_t)w * E_ + j]);
}

__global__ void zero_state() {
    int i = blockIdx.x * 256 + threadIdx.x;   // 65536
    g_hbig[i] = __float2half_rn(0.f);         // slot 0 = h(0) = 0
    g_c[i] = 0.f;                             // parity 0
}

// ---------------------------------------------------------------------------
extern "C" void kernel_launch(void* const* d_in, const int* in_sizes, int n_in,
                              void* d_out, int out_size) {
    const int*   captions = (const int*)d_in[0];
    const float* enc      = (const float*)d_in[1];
    const float* emb      = (const float*)d_in[2];
    const float* W_h      = (const float*)d_in[3];
    const float* W_e      = (const float*)d_in[4];
    const float* v_attn   = (const float*)d_in[5];
    const float* W_ih     = (const float*)d_in[6];
    const float* W_hh     = (const float*)d_in[7];
    const float* b_ih     = (const float*)d_in[8];
    const float* b_hh     = (const float*)d_in[9];
    const float* W_fc     = (const float*)d_in[10];
    const float* b_fc     = (const float*)d_in[11];
    float* out = (float*)d_out;

    static cudaStream_t s2 = nullptr, s3 = nullptr, s4 = nullptr;
    static cudaEvent_t evStart = nullptr, evG = nullptr, evH = nullptr,
                       evW = nullptr, evJ2 = nullptr, evJ4 = nullptr;
    if (!s2) {
        cudaStreamCreateWithFlags(&s2, cudaStreamNonBlocking);
        cudaStreamCreateWithFlags(&s3, cudaStreamNonBlocking);
        cudaStreamCreateWithFlags(&s4, cudaStreamNonBlocking);
        cudaEventCreateWithFlags(&evStart, cudaEventDisableTiming);
        cudaEventCreateWithFlags(&evG,  cudaEventDisableTiming);
        cudaEventCreateWithFlags(&evH,  cudaEventDisableTiming);
        cudaEventCreateWithFlags(&evW,  cudaEventDisableTiming);
        cudaEventCreateWithFlags(&evJ2, cudaEventDisableTiming);
        cudaEventCreateWithFlags(&evJ4, cudaEventDisableTiming);
    }
    cudaFuncSetAttribute(mma_gemm<128>,
                         cudaFuncAttributeMaxDynamicSharedMemorySize, SMEM128_);
    cudaFuncSetAttribute(mma_gemm<32>,
                         cudaFuncAttributeMaxDynamicSharedMemorySize, SMEM32_);
    cudaFuncSetAttribute(gemm2_lstm,
                         cudaFuncAttributeMaxDynamicSharedMemorySize, SMEM32_);

    float *enc_proj, *gates_pre, *bsum;
    __half *Wbig, *hbig, *W1H, *encA, *embX, *WeB, *WihB;
    cudaGetSymbolAddress((void**)&enc_proj,  g_enc_proj);
    cudaGetSymbolAddress((void**)&gates_pre, g_gates_pre);
    cudaGetSymbolAddress((void**)&bsum,      g_bsum);
    cudaGetSymbolAddress((void**)&Wbig,      g_Wbig);
    cudaGetSymbolAddress((void**)&hbig,      g_hbig);
    cudaGetSymbolAddress((void**)&W1H,       g_W1H);
    cudaGetSymbolAddress((void**)&encA,      g_encA);
    cudaGetSymbolAddress((void**)&embX,      g_embX);
    cudaGetSymbolAddress((void**)&WeB,       g_WeB);
    cudaGetSymbolAddress((void**)&WihB,      g_WihB);
    float* big1; cudaGetSymbolAddress((void**)&big1, g_big1);

    // fork: all side streams join the capture BEFORE any of their work
    zero_state<<<256, 256>>>();
    cudaEventRecord(evStart, 0);
    cudaStreamWaitEvent(s2, evStart, 0);
    cudaStreamWaitEvent(s3, evStart, 0);
    cudaStreamWaitEvent(s4, evStart, 0);

    // s2: W_fc fp16 (feeds logits on both logits streams)
    wfc_conv<<<VPAD_, 512, 0, s2>>>(W_fc);
    cudaEventRecord(evW, s2);
    cudaStreamWaitEvent(s4, evW, 0);

    // s3: gates_pre pipeline
    bias_sum_perm<<<8, 256, 0, s3>>>(b_ih, b_hh);
    emb_gather<<<BT_, 512, 0, s3>>>(captions, emb);
    wih_emb_conv<<<4 * H_, 512, 0, s3>>>(W_ih);
    mma_gemm<128><<<dim3(16, T_), 256, SMEM128_, s3>>>(
        embX, WihB, bsum, gates_pre, 4L * H_, 4 * H_);
    cudaEventRecord(evG, s3);

    // s1: chain weights + enc_proj
    w1h_conv<<<2560, 512>>>(W_h, W_hh);
    w2_conv<<<2048, 512>>>(W_ih);
    h16_conv<<<H_, 512>>>(W_e, WeB);
    h16_conv<<<BL_, 512>>>(enc, encA);
    mma_gemm<128><<<dim3(4, BL_ / 128), 256, SMEM128_>>>(
        encA, WeB, nullptr, enc_proj, (long)H_, H_);

    cudaStream_t sL[2] = {s2, s4};
    for (int t = 0; t < T_; t++) {
        // gemm1: big1 = h(t) @ [W_h | perm(W_hh)]^T  (BN=32, 80 CTAs)
        mma_gemm<32><<<dim3(80, 1), 256, SMEM32_>>>(
            hbig + (size_t)t * B_ * 512, W1H, nullptr, big1, 2560L, 2560);
        attn_kernel<<<B_, 512>>>(enc, v_attn);
        if (t == 0) cudaStreamWaitEvent(0, evG, 0);   // join s3 (gates_pre)
        gemm2_lstm<<<dim3(64, 1), 256, SMEM32_>>>(t);
        cudaEventRecord(evH, 0);
        cudaStreamWaitEvent(sL[t & 1], evH, 0);
        // logits: single-term fp16, K=512, 79 CTAs, alternating streams
        mma_gemm<128><<<dim3(79, 1), 256, SMEM128_, sL[t & 1]>>>(
            hbig + (size_t)(t + 1) * B_ * 512, Wbig, b_fc,
            out + (size_t)t * V_, (long)(T_ * V_), V_);
    }
    cudaEventRecord(evJ2, s2);
    cudaStreamWaitEvent(0, evJ2, 0);
    cudaEventRecord(evJ4, s4);
    cudaStreamWaitEvent(0, evJ4, 0);
}

// round 13
// speedup vs baseline: 1.0853x; 1.0853x over previous
#include <cuda_runtime.h>
#include <cuda_fp16.h>
#include <cstdint>

#define B_    128
#define T_    25
#define L_    49
#define V_    10000
#define E_    512
#define H_    512
#define ENC_  512
#define BL_   (B_ * L_)      // 6272
#define BT_   (B_ * T_)      // 3200
#define VPAD_ 10112          // 79 * 128

typedef unsigned long long ull;

// ---------------- device scratch ----------------
__device__ float g_enc_proj[BL_ * H_];              // [6272][512]
__device__ float g_gates_pre[(size_t)BT_ * 4 * H_]; // [3200][2048] permuted cols
__device__ float g_bsum[4 * H_];                    // permuted
__device__ float g_big1[B_ * 2560];                 // [128][hp(512)|gates_h(2048)]
__device__ float g_c[2 * B_ * H_];
// fp16 HMMA operands (single-term, row-major [N][512])
__device__ __align__(16) __half g_Wbig[(size_t)VPAD_ * 512];
__device__ __align__(16) __half g_hbig[(size_t)(T_ + 1) * B_ * 512];
__device__ __align__(16) __half g_W1H[2560 * 512];  // [W_h | perm(W_hh)]
__device__ __align__(16) __half g_W2H[2048 * 512];  // perm(W_ih[:,512:])
__device__ __align__(16) __half g_ctxH[B_ * 512];
__device__ __align__(16) __half g_encA[(size_t)BL_ * 512];
__device__ __align__(16) __half g_embX[(size_t)BT_ * 512];
__device__ __align__(16) __half g_WeB[(size_t)H_ * 512];
__device__ __align__(16) __half g_WihB[(size_t)(4 * H_) * 512];

// ---------------- fast transcendentals ----------------
__device__ __forceinline__ float fex2(float x) {
    float y; asm("ex2.approx.ftz.f32 %0, %1;" : "=f"(y) : "f"(x)); return y;
}
__device__ __forceinline__ float frcp(float x) {
    float y; asm("rcp.approx.ftz.f32 %0, %1;" : "=f"(y) : "f"(x)); return y;
}
__device__ __forceinline__ float ftanh_hw(float x) {
    float y; asm("tanh.approx.f32 %0, %1;" : "=f"(y) : "f"(x)); return y;
}
__device__ __forceinline__ float ftanh(float x) {
    float xc = fminf(fmaxf(x, -8.f), 8.f);
    float e = fex2(xc * 2.8853900817779268f);
    return (e - 1.f) * frcp(e + 1.f);
}
__device__ __forceinline__ float fsig(float x) {
    float xc = fminf(fmaxf(x, -30.f), 30.f);
    float e = fex2(-xc * 1.4426950408889634f);
    return frcp(1.f + e);
}

// ---------------- mma.sync helpers ----------------
__device__ __forceinline__ uint32_t smem_u32(const void* p) {
    uint32_t a;
    asm("{ .reg .u64 t; cvta.to.shared.u64 t, %1; cvt.u32.u64 %0, t; }"
        : "=r"(a) : "l"(p));
    return a;
}
__device__ __forceinline__ void ldm_x4(uint32_t* r, uint32_t addr) {
    asm volatile("ldmatrix.sync.aligned.m8n8.x4.shared.b16 {%0,%1,%2,%3}, [%4];"
        : "=r"(r[0]), "=r"(r[1]), "=r"(r[2]), "=r"(r[3]) : "r"(addr));
}
__device__ __forceinline__ void ldm_x2(uint32_t* r, uint32_t addr) {
    asm volatile("ldmatrix.sync.aligned.m8n8.x2.shared.b16 {%0,%1}, [%2];"
        : "=r"(r[0]), "=r"(r[1]) : "r"(addr));
}
__device__ __forceinline__ void mma_f16(float* d, const uint32_t* a,
                                        uint32_t b0, uint32_t b1) {
    asm volatile("mma.sync.aligned.m16n8k16.row.col.f32.f16.f16.f32 "
        "{%0,%1,%2,%3}, {%4,%5,%6,%7}, {%8,%9}, {%0,%1,%2,%3};"
        : "+f"(d[0]), "+f"(d[1]), "+f"(d[2]), "+f"(d[3])
        : "r"(a[0]), "r"(a[1]), "r"(a[2]), "r"(a[3]), "r"(b0), "r"(b1));
}
__device__ __forceinline__ void cp16(uint32_t dst, const void* src) {
    asm volatile("cp.async.cg.shared.global [%0], [%1], 16;"
                 :: "r"(dst), "l"(src));
}

#define KLEN_  512
#define NCH_   8                     // K=64 per chunk
#define PITCH_ 144                   // 128B data + 16B pad (conflict-free LDSM)
#define SMEM128_ (4 * 256 * PITCH_)  // BN=128: 147456 B
#define SMEM32_  (4 * 160 * PITCH_)  // BN=32:   92160 B

// ---------------------------------------------------------------------------
// Templated HMMA mainloop: CTA 128m x BN n, K=512 in 8 chunks of 64,
// 8 warps (2m x 4n), cp.async 4-stage pipeline. Results cx.d[4][FN][4].
// ---------------------------------------------------------------------------
template<int BN>
struct MmaCtx {
    static constexpr int FN = BN / 32;   // n8 fragments per warp
    float d[4][FN][4];
    int arow, acol, l, wm, wn;
    uint32_t sb;
};

template<int BN>
__device__ __forceinline__ void mma_mainloop(
    MmaCtx<BN>& cx, const __half* Asrc, const __half* Bsrc, __half* smh)
{
    constexpr int FN = BN / 32;
    constexpr int ROWS = 128 + BN;
    constexpr int STAGE = ROWS * PITCH_;
    constexpr int NW = BN / 4;           // n per warp
    constexpr int NLD = ROWS * 8 / 256;  // cp16 per thread per chunk
    const int tid = threadIdx.x;
    const int l = tid & 31, wid = tid >> 5;
    cx.l = l; cx.wm = wid >> 2; cx.wn = wid & 3;
    cx.sb = smem_u32(smh);
#pragma unroll
    for (int i = 0; i < 4; i++)
#pragma unroll
        for (int j = 0; j < FN; j++)
#pragma unroll
            for (int q = 0; q < 4; q++) cx.d[i][j][q] = 0.f;

    cx.arow = cx.wm * 64 + (l & 15);
    cx.acol = (l >> 4) * 8;
    const int brow4 = cx.wn * NW + ((l >> 4) << 3) + (l & 7);  // x4 path
    const int bcol4 = ((l >> 3) & 1) * 8;
    const int brow2 = cx.wn * NW + (l & 7);                    // x2 path
    const int bcol2 = ((l >> 3) & 1) * 8;

    const int lr  = tid >> 3;            // row step: +32 per q
    const int lsg = (tid & 7) * 8;       // 16B segment (in halves)

    auto issue_chunk = [&](int c, int buf) {
        const uint32_t dbase = cx.sb + buf * STAGE;
#pragma unroll
        for (int q = 0; q < NLD; q++) {
            int r = lr + q * 32;
            const __half* s = (r < 128) ? (Asrc + (size_t)r * KLEN_)
                                        : (Bsrc + (size_t)(r - 128) * KLEN_);
            cp16(dbase + r * PITCH_ + lsg * 2, s + c * 64 + lsg);
        }
        asm volatile("cp.async.commit_group;" ::: "memory");
    };

    issue_chunk(0, 0);
    issue_chunk(1, 1);
    issue_chunk(2, 2);

#pragma unroll 1
    for (int c = 0; c < NCH_; c++) {
        if (c + 3 < NCH_) asm volatile("cp.async.wait_group 2;" ::: "memory");
        else              asm volatile("cp.async.wait_group 0;" ::: "memory");
        __syncthreads();
        if (c + 3 < NCH_) issue_chunk(c + 3, (c + 3) & 3);
        const uint32_t base = cx.sb + (c & 3) * STAGE;
#pragma unroll
        for (int s = 0; s < 4; s++) {
            uint32_t ar[4][4];
#pragma unroll
            for (int fm = 0; fm < 4; fm++)
                ldm_x4(ar[fm], base + (cx.arow + fm * 16) * PITCH_
                                    + (cx.acol + s * 16) * 2);
            uint32_t br[2 * FN];
            if (FN == 1) {
                ldm_x2(br, base + 128 * PITCH_ + brow2 * PITCH_
                                + (bcol2 + s * 16) * 2);
            } else {
#pragma unroll
                for (int fp = 0; fp < FN / 2; fp++)
                    ldm_x4(br + 4 * fp, base + 128 * PITCH_
                           + (brow4 + fp * 16) * PITCH_ + (bcol4 + s * 16) * 2);
            }
#pragma unroll
            for (int fn = 0; fn < FN; fn++)
#pragma unroll
                for (int fm = 0; fm < 4; fm++)
                    mma_f16(cx.d[fm][fn], ar[fm], br[2 * fn], br[2 * fn + 1]);
        }
    }
}

// ---------------------------------------------------------------------------
// Generic GEMM (fp32 out, optional bias). grid(N/BN, M/128).
// ---------------------------------------------------------------------------
template<int BN>
__global__ void __launch_bounds__(256) mma_gemm(
    const __half* __restrict__ A, const __half* __restrict__ Bm,
    const float* __restrict__ bias, float* __restrict__ out,
    long ldout, int Nvalid)
{
    extern __shared__ __align__(16) __half smh[];
    const int mbase = blockIdx.y * 128;
    const int nbase = blockIdx.x * BN;
    MmaCtx<BN> cx;
    mma_mainloop<BN>(cx, A + (size_t)mbase * KLEN_,
                     Bm + (size_t)nbase * KLEN_, smh);

#pragma unroll
    for (int fm = 0; fm < 4; fm++) {
        int m0 = mbase + cx.wm * 64 + fm * 16 + (cx.l >> 2);
#pragma unroll
        for (int fn = 0; fn < MmaCtx<BN>::FN; fn++) {
            int n0 = nbase + cx.wn * (BN / 4) + fn * 8 + (cx.l & 3) * 2;
            if (n0 < Nvalid) {
                float b0 = bias ? bias[n0] : 0.f;
                float b1 = bias ? bias[n0 + 1] : 0.f;
                float2 v0 = make_float2(cx.d[fm][fn][0] + b0, cx.d[fm][fn][1] + b1);
                float2 v1 = make_float2(cx.d[fm][fn][2] + b0, cx.d[fm][fn][3] + b1);
                *(float2*)&out[(size_t)m0 * ldout + n0] = v0;
                *(float2*)&out[(size_t)(m0 + 8) * ldout + n0] = v1;
            }
        }
    }
}

// ---------------------------------------------------------------------------
// gemm2 + LSTM pointwise fused (BN=32). grid(64): nbase = bx*32 gate-cols.
// ---------------------------------------------------------------------------
__global__ void __launch_bounds__(256) gemm2_lstm(int t) {
    extern __shared__ __align__(16) __half smh[];
    const int nbase = blockIdx.x * 32;
    MmaCtx<32> cx;
    mma_mainloop<32>(cx, g_ctxH, g_W2H + (size_t)nbase * KLEN_, smh);

    __syncthreads();                        // pipeline smem -> gates smem reuse
    float* gsm = reinterpret_cast<float*>(smh);   // [128][33]
#pragma unroll
    for (int fm = 0; fm < 4; fm++) {
        int m0 = cx.wm * 64 + fm * 16 + (cx.l >> 2);
        int n0 = cx.wn * 8 + (cx.l & 3) * 2;
#pragma unroll
        for (int hh = 0; hh < 2; hh++) {
            int m = m0 + hh * 8;
            const float* pre =
                &g_gates_pre[((size_t)(t * B_ + m)) * 2048 + nbase + n0];
            const float* bh = &g_big1[m * 2560 + 512 + nbase + n0];
            gsm[m * 33 + n0]     = cx.d[fm][0][hh * 2]     + bh[0] + pre[0];
            gsm[m * 33 + n0 + 1] = cx.d[fm][0][hh * 2 + 1] + bh[1] + pre[1];
        }
    }
    __syncthreads();

    const int tid = threadIdx.x;
#pragma unroll
    for (int q = 0; q < 4; q++) {
        int idx = tid + q * 256;
        int b = idx >> 3, ul = idx & 7;     // 128 b x 8 units
        int u = (nbase >> 2) + ul;
        float gi = gsm[b * 33 + ul * 4 + 0];
        float gf = gsm[b * 33 + ul * 4 + 1];
        float gg = gsm[b * 33 + ul * 4 + 2];
        float go = gsm[b * 33 + ul * 4 + 3];
        float cn = fsig(gf) * g_c[(size_t)(t & 1) * (B_ * H_) + b * H_ + u]
                 + fsig(gi) * ftanh(gg);
        g_c[(size_t)((t + 1) & 1) * (B_ * H_) + b * H_ + u] = cn;
        float h = fsig(go) * ftanh(cn);
        g_hbig[(size_t)(t + 1) * (B_ * 512) + b * 512 + u] = __float2half_rn(h);
    }
}

// ---------------------------------------------------------------------------
// Attention: hp from big1[:, 0:512]; scores; softmax; ctx -> ctxH fp16.
// ---------------------------------------------------------------------------
__global__ void __launch_bounds__(512) attn_kernel(
    const float* __restrict__ enc, const float* __restrict__ vattn) {
    const int b = blockIdx.x, tid = threadIdx.x;
    __shared__ float hp_s[H_];
    __shared__ float v_s[H_];
    __shared__ float sc[64];

    hp_s[tid] = g_big1[b * 2560 + tid];
    v_s[tid] = vattn[tid];
    __syncthreads();

    const int w = tid >> 5, lane = tid & 31;
    const float* ep = g_enc_proj + (size_t)b * L_ * H_;
    for (int l = w; l < L_; l += 16) {
        const float* row = ep + l * H_;
        float p = 0.f;
#pragma unroll
        for (int k = lane; k < H_; k += 32)
            p += ftanh_hw(hp_s[k] + row[k]) * v_s[k];
#pragma unroll
        for (int o = 16; o; o >>= 1) p += __shfl_xor_sync(0xffffffffu, p, o);
        if (lane == 0) sc[l] = p;
    }
    __syncthreads();

    if (tid < 32) {
        float v0 = sc[tid];
        float v1 = (tid < L_ - 32) ? sc[32 + tid] : -1e30f;
        float mx = fmaxf(v0, v1);
#pragma unroll
        for (int o = 16; o; o >>= 1) mx = fmaxf(mx, __shfl_xor_sync(0xffffffffu, mx, o));
        float e0 = fex2((v0 - mx) * 1.4426950408889634f);
        float e1 = (tid < L_ - 32) ? fex2((v1 - mx) * 1.4426950408889634f) : 0.f;
        float s = e0 + e1;
#pragma unroll
        for (int o = 16; o; o >>= 1) s += __shfl_xor_sync(0xffffffffu, s, o);
        float r = frcp(s);
        sc[tid] = e0 * r;
        if (tid < L_ - 32) sc[32 + tid] = e1 * r;
    }
    __syncthreads();

    const float* eb = enc + (size_t)b * L_ * ENC_;
    float a = 0.f;
#pragma unroll 7
    for (int l = 0; l < L_; l++) a += sc[l] * eb[l * ENC_ + tid];
    g_ctxH[b * 512 + tid] = __float2half_rn(a);
}

// ---------------------------------------------------------------------------
// preamble kernels (fp16 converts)
// ---------------------------------------------------------------------------
__global__ void bias_sum_perm(const float* __restrict__ bi,
                              const float* __restrict__ bh) {
    int n = blockIdx.x * 256 + threadIdx.x;
    int o = ((n & 3) << 9) | (n >> 2);
    g_bsum[n] = bi[o] + bh[o];
}

__global__ void wfc_conv(const float* __restrict__ W_fc) {
    int n = blockIdx.x, j = threadIdx.x;
    float w = (n < V_) ? W_fc[(size_t)n * H_ + j] : 0.f;
    g_Wbig[(size_t)n * 512 + j] = __float2half_rn(w);
}

__global__ void w1h_conv(const float* __restrict__ W_h,
                         const float* __restrict__ W_hh) {
    int n = blockIdx.x, j = threadIdx.x;
    float w;
    if (n < 512) w = W_h[(size_t)n * H_ + j];
    else {
        int p = n - 512;
        int o = ((p & 3) << 9) | (p >> 2);
        w = W_hh[(size_t)o * H_ + j];
    }
    g_W1H[(size_t)n * 512 + j] = __float2half_rn(w);
}

__global__ void w2_conv(const float* __restrict__ W_ih) {
    int n = blockIdx.x, j = threadIdx.x;
    int o = ((n & 3) << 9) | (n >> 2);
    g_W2H[(size_t)n * 512 + j] = __float2half_rn(W_ih[(size_t)o * 1024 + 512 + j]);
}

__global__ void wih_emb_conv(const float* __restrict__ W_ih) {
    int n = blockIdx.x, j = threadIdx.x;
    int o = ((n & 3) << 9) | (n >> 2);
    g_WihB[(size_t)n * 512 + j] = __float2half_rn(W_ih[(size_t)o * 1024 + j]);
}

__global__ void h16_conv(const float* __restrict__ src, __half* __restrict__ dst) {
    int m = blockIdx.x, j = threadIdx.x;
    dst[(size_t)m * 512 + j] = __float2half_rn(src[(size_t)m * 512 + j]);
}

__global__ void emb_gather(const int* __restrict__ cap, const float* __restrict__ emb) {
    int m = blockIdx.x;
    int b = m & 127, t = m >> 7;
    int w = cap[b * T_ + t];
    int j = threadIdx.x;
    g_embX[(size_t)m * 512 + j] = __float2half_rn(emb[(size_t)w * E_ + j]);
}

__global__ void zero_state() {
    int i = blockIdx.x * 256 + threadIdx.x;   // 65536
    g_hbig[i] = __float2half_rn(0.f);         // slot 0 = h(0) = 0
    g_c[i] = 0.f;                             // parity 0
}

// ---------------------------------------------------------------------------
extern "C" void kernel_launch(void* const* d_in, const int* in_sizes, int n_in,
                              void* d_out, int out_size) {
    const int*   captions = (const int*)d_in[0];
    const float* enc      = (const float*)d_in[1];
    const float* emb      = (const float*)d_in[2];
    const float* W_h      = (const float*)d_in[3];
    const float* W_e      = (const float*)d_in[4];
    const float* v_attn   = (const float*)d_in[5];
    const float* W_ih     = (const float*)d_in[6];
    const float* W_hh     = (const float*)d_in[7];
    const float* b_ih     = (const float*)d_in[8];
    const float* b_hh     = (const float*)d_in[9];
    const float* W_fc     = (const float*)d_in[10];
    const float* b_fc     = (const float*)d_in[11];
    float* out = (float*)d_out;

    static cudaStream_t s2 = nullptr, s3 = nullptr, s4 = nullptr;
    static cudaEvent_t evStart = nullptr, evG = nullptr, evH = nullptr,
                       evW = nullptr, evJ2 = nullptr, evJ4 = nullptr;
    if (!s2) {
        cudaStreamCreateWithFlags(&s2, cudaStreamNonBlocking);
        cudaStreamCreateWithFlags(&s3, cudaStreamNonBlocking);
        cudaStreamCreateWithFlags(&s4, cudaStreamNonBlocking);
        cudaEventCreateWithFlags(&evStart, cudaEventDisableTiming);
        cudaEventCreateWithFlags(&evG,  cudaEventDisableTiming);
        cudaEventCreateWithFlags(&evH,  cudaEventDisableTiming);
        cudaEventCreateWithFlags(&evW,  cudaEventDisableTiming);
        cudaEventCreateWithFlags(&evJ2, cudaEventDisableTiming);
        cudaEventCreateWithFlags(&evJ4, cudaEventDisableTiming);
    }
    cudaFuncSetAttribute(mma_gemm<128>,
                         cudaFuncAttributeMaxDynamicSharedMemorySize, SMEM128_);
    cudaFuncSetAttribute(mma_gemm<32>,
                         cudaFuncAttributeMaxDynamicSharedMemorySize, SMEM32_);
    cudaFuncSetAttribute(gemm2_lstm,
                         cudaFuncAttributeMaxDynamicSharedMemorySize, SMEM32_);

    float *enc_proj, *gates_pre, *bsum;
    __half *Wbig, *hbig, *W1H, *encA, *embX, *WeB, *WihB;
    cudaGetSymbolAddress((void**)&enc_proj,  g_enc_proj);
    cudaGetSymbolAddress((void**)&gates_pre, g_gates_pre);
    cudaGetSymbolAddress((void**)&bsum,      g_bsum);
    cudaGetSymbolAddress((void**)&Wbig,      g_Wbig);
    cudaGetSymbolAddress((void**)&hbig,      g_hbig);
    cudaGetSymbolAddress((void**)&W1H,       g_W1H);
    cudaGetSymbolAddress((void**)&encA,      g_encA);
    cudaGetSymbolAddress((void**)&embX,      g_embX);
    cudaGetSymbolAddress((void**)&WeB,       g_WeB);
    cudaGetSymbolAddress((void**)&WihB,      g_WihB);
    float* big1; cudaGetSymbolAddress((void**)&big1, g_big1);

    // fork: all side streams join the capture BEFORE any of their work
    zero_state<<<256, 256>>>();
    cudaEventRecord(evStart, 0);
    cudaStreamWaitEvent(s2, evStart, 0);
    cudaStreamWaitEvent(s3, evStart, 0);
    cudaStreamWaitEvent(s4, evStart, 0);

    // s2: W_fc fp16 (feeds logits on both logits streams)
    wfc_conv<<<VPAD_, 512, 0, s2>>>(W_fc);
    cudaEventRecord(evW, s2);
    cudaStreamWaitEvent(s4, evW, 0);

    // s3: gates_pre pipeline
    bias_sum_perm<<<8, 256, 0, s3>>>(b_ih, b_hh);
    emb_gather<<<BT_, 512, 0, s3>>>(captions, emb);
    wih_emb_conv<<<4 * H_, 512, 0, s3>>>(W_ih);
    mma_gemm<128><<<dim3(16, T_), 256, SMEM128_, s3>>>(
        embX, WihB, bsum, gates_pre, 4L * H_, 4 * H_);
    cudaEventRecord(evG, s3);

    // s1: chain weights + enc_proj
    w1h_conv<<<2560, 512>>>(W_h, W_hh);
    w2_conv<<<2048, 512>>>(W_ih);
    h16_conv<<<H_, 512>>>(W_e, WeB);
    h16_conv<<<BL_, 512>>>(enc, encA);
    mma_gemm<128><<<dim3(4, BL_ / 128), 256, SMEM128_>>>(
        encA, WeB, nullptr, enc_proj, (long)H_, H_);

    cudaStream_t sL[2] = {s2, s4};
    for (int t = 0; t < T_; t++) {
        // gemm1: big1 = h(t) @ [W_h | perm(W_hh)]^T  (BN=32, 80 CTAs)
        mma_gemm<32><<<dim3(80, 1), 256, SMEM32_>>>(
            hbig + (size_t)t * B_ * 512, W1H, nullptr, big1, 2560L, 2560);
        attn_kernel<<<B_, 512>>>(enc, v_attn);
        if (t == 0) cudaStreamWaitEvent(0, evG, 0);   // join s3 (gates_pre)
        gemm2_lstm<<<dim3(64, 1), 256, SMEM32_>>>(t);
        cudaEventRecord(evH, 0);
        cudaStreamWaitEvent(sL[t & 1], evH, 0);
        // logits: single-term fp16, K=512, 79 CTAs, alternating streams
        mma_gemm<128><<<dim3(79, 1), 256, SMEM128_, sL[t & 1]>>>(
            hbig + (size_t)(t + 1) * B_ * 512, Wbig, b_fc,
            out + (size_t)t * V_, (long)(T_ * V_), V_);
    }
    cudaEventRecord(evJ2, s2);
    cudaStreamWaitEvent(0, evJ2, 0);
    cudaEventRecord(evJ4, s4);
    cudaStreamWaitEvent(0, evJ4, 0);
}

// round 16
// speedup vs baseline: 1.1069x; 1.0199x over previous
#include <cuda_runtime.h>
#include <cuda_fp16.h>
#include <cstdint>

#define B_    128
#define T_    25
#define L_    49
#define V_    10000
#define E_    512
#define H_    512
#define ENC_  512
#define BL_   (B_ * L_)      // 6272
#define BT_   (B_ * T_)      // 3200
#define VPAD_ 10112          // 79 * 128

typedef unsigned long long ull;

// ---------------- device scratch ----------------
__device__ float g_enc_proj[BL_ * H_];              // [6272][512]
__device__ float g_gates_pre[(size_t)BT_ * 4 * H_]; // [3200][2048] permuted cols
__device__ float g_bsum[4 * H_];                    // permuted
__device__ float g_big1[B_ * 2560];                 // [128][hp(512)|gates_h(2048)]
__device__ float g_c[2 * B_ * H_];
// fp16 HMMA operands (single-term, row-major [N][512])
__device__ __align__(16) __half g_Wbig[(size_t)VPAD_ * 512];
__device__ __align__(16) __half g_hbig[(size_t)(T_ + 1) * B_ * 512];
__device__ __align__(16) __half g_W1H[2560 * 512];  // [W_h | perm(W_hh)]
__device__ __align__(16) __half g_W2H[2048 * 512];  // perm(W_ih[:,512:])
__device__ __align__(16) __half g_ctxH[B_ * 512];
__device__ __align__(16) __half g_encA[(size_t)BL_ * 512];
__device__ __align__(16) __half g_embX[(size_t)BT_ * 512];
__device__ __align__(16) __half g_WeB[(size_t)H_ * 512];
__device__ __align__(16) __half g_WihB[(size_t)(4 * H_) * 512];

// ---------------- fast transcendentals ----------------
__device__ __forceinline__ float fex2(float x) {
    float y; asm("ex2.approx.ftz.f32 %0, %1;" : "=f"(y) : "f"(x)); return y;
}
__device__ __forceinline__ float frcp(float x) {
    float y; asm("rcp.approx.ftz.f32 %0, %1;" : "=f"(y) : "f"(x)); return y;
}
__device__ __forceinline__ float ftanh_hw(float x) {
    float y; asm("tanh.approx.f32 %0, %1;" : "=f"(y) : "f"(x)); return y;
}
__device__ __forceinline__ float ftanh(float x) {
    float xc = fminf(fmaxf(x, -8.f), 8.f);
    float e = fex2(xc * 2.8853900817779268f);
    return (e - 1.f) * frcp(e + 1.f);
}
__device__ __forceinline__ float fsig(float x) {
    float xc = fminf(fmaxf(x, -30.f), 30.f);
    float e = fex2(-xc * 1.4426950408889634f);
    return frcp(1.f + e);
}

// ---------------- mma.sync helpers ----------------
__device__ __forceinline__ uint32_t smem_u32(const void* p) {
    uint32_t a;
    asm("{ .reg .u64 t; cvta.to.shared.u64 t, %1; cvt.u32.u64 %0, t; }"
        : "=r"(a) : "l"(p));
    return a;
}
__device__ __forceinline__ void ldm_x4(uint32_t* r, uint32_t addr) {
    asm volatile("ldmatrix.sync.aligned.m8n8.x4.shared.b16 {%0,%1,%2,%3}, [%4];"
        : "=r"(r[0]), "=r"(r[1]), "=r"(r[2]), "=r"(r[3]) : "r"(addr));
}
__device__ __forceinline__ void ldm_x2(uint32_t* r, uint32_t addr) {
    asm volatile("ldmatrix.sync.aligned.m8n8.x2.shared.b16 {%0,%1}, [%2];"
        : "=r"(r[0]), "=r"(r[1]) : "r"(addr));
}
__device__ __forceinline__ void mma_f16(float* d, const uint32_t* a,
                                        uint32_t b0, uint32_t b1) {
    asm volatile("mma.sync.aligned.m16n8k16.row.col.f32.f16.f16.f32 "
        "{%0,%1,%2,%3}, {%4,%5,%6,%7}, {%8,%9}, {%0,%1,%2,%3};"
        : "+f"(d[0]), "+f"(d[1]), "+f"(d[2]), "+f"(d[3])
        : "r"(a[0]), "r"(a[1]), "r"(a[2]), "r"(a[3]), "r"(b0), "r"(b1));
}
__device__ __forceinline__ void cp16(uint32_t dst, const void* src) {
    asm volatile("cp.async.cg.shared.global [%0], [%1], 16;"
                 :: "r"(dst), "l"(src));
}

#define KLEN_ 512
#define SMEM128_ (4 * 256 * 144)    // BN=128, KCH=64:  147456 B
#define SMEM32_  (4 * 160 * 272)    // BN=32,  KCH=128: 174080 B

// ---------------------------------------------------------------------------
// Templated HMMA mainloop: CTA 128m x BN n, K=512 in chunks of KCH,
// 8 warps (2m x 4n), cp.async 4-stage pipeline. Results cx.d[4][FN][4].
// ---------------------------------------------------------------------------
template<int BN>
struct MmaCtx {
    static constexpr int FN = BN / 32;   // n8 fragments per warp
    float d[4][FN][4];
    int arow, acol, l, wm, wn;
    uint32_t sb;
};

template<int BN, int KCH>
__device__ __forceinline__ void mma_mainloop(
    MmaCtx<BN>& cx, const __half* Asrc, const __half* Bsrc, __half* smh)
{
    constexpr int FN = BN / 32;
    constexpr int ROWS = 128 + BN;
    constexpr int PITCH = (KCH == 64) ? 144 : 272;  // data + 16B pad
    constexpr int STAGE = ROWS * PITCH;
    constexpr int NCH = 512 / KCH;
    constexpr int SEGS = KCH / 8;        // 16B segments per row-chunk
    constexpr int SSTEPS = KCH / 16;     // k16 steps per chunk
    constexpr int NLD = ROWS * SEGS / 256;
    constexpr int NW = BN / 4;
    const int tid = threadIdx.x;
    const int l = tid & 31, wid = tid >> 5;
    cx.l = l; cx.wm = wid >> 2; cx.wn = wid & 3;
    cx.sb = smem_u32(smh);
#pragma unroll
    for (int i = 0; i < 4; i++)
#pragma unroll
        for (int j = 0; j < FN; j++)
#pragma unroll
            for (int q = 0; q < 4; q++) cx.d[i][j][q] = 0.f;

    cx.arow = cx.wm * 64 + (l & 15);
    cx.acol = (l >> 4) * 8;
    const int brow4 = cx.wn * NW + ((l >> 4) << 3) + (l & 7);  // x4 path
    const int bcol4 = ((l >> 3) & 1) * 8;
    const int brow2 = cx.wn * NW + (l & 7);                    // x2 path
    const int bcol2 = ((l >> 3) & 1) * 8;

    const int lr  = tid / SEGS;
    const int lsg = (tid % SEGS) * 8;    // in halves

    auto issue_chunk = [&](int c, int buf) {
        const uint32_t dbase = cx.sb + buf * STAGE;
#pragma unroll
        for (int q = 0; q < NLD; q++) {
            int r = lr + q * (256 / SEGS);
            const __half* s = (r < 128) ? (Asrc + (size_t)r * KLEN_)
                                        : (Bsrc + (size_t)(r - 128) * KLEN_);
            cp16(dbase + r * PITCH + lsg * 2, s + c * KCH + lsg);
        }
        asm volatile("cp.async.commit_group;" ::: "memory");
    };

    issue_chunk(0, 0);
    issue_chunk(1, 1);
    issue_chunk(2, 2);

#pragma unroll 1
    for (int c = 0; c < NCH; c++) {
        if (c + 3 <= NCH)      asm volatile("cp.async.wait_group 2;" ::: "memory");
        else if (c + 2 == NCH) asm volatile("cp.async.wait_group 1;" ::: "memory");
        else                   asm volatile("cp.async.wait_group 0;" ::: "memory");
        __syncthreads();
        if (c + 3 < NCH) issue_chunk(c + 3, (c + 3) & 3);
        const uint32_t base = cx.sb + (c & 3) * STAGE;
#pragma unroll
        for (int s = 0; s < SSTEPS; s++) {
            uint32_t ar[4][4];
#pragma unroll
            for (int fm = 0; fm < 4; fm++)
                ldm_x4(ar[fm], base + (cx.arow + fm * 16) * PITCH
                                    + (cx.acol + s * 16) * 2);
            uint32_t br[2 * FN];
            if (FN == 1) {
                ldm_x2(br, base + 128 * PITCH + brow2 * PITCH
                                + (bcol2 + s * 16) * 2);
            } else {
#pragma unroll
                for (int fp = 0; fp < FN / 2; fp++)
                    ldm_x4(br + 4 * fp, base + 128 * PITCH
                           + (brow4 + fp * 16) * PITCH + (bcol4 + s * 16) * 2);
            }
#pragma unroll
            for (int fn = 0; fn < FN; fn++)
#pragma unroll
                for (int fm = 0; fm < 4; fm++)
                    mma_f16(cx.d[fm][fn], ar[fm], br[2 * fn], br[2 * fn + 1]);
        }
    }
}

// ---------------------------------------------------------------------------
// Generic GEMM (fp32 out, optional bias). grid(N/BN, M/128).
// ---------------------------------------------------------------------------
template<int BN, int KCH>
__global__ void __launch_bounds__(256) mma_gemm(
    const __half* __restrict__ A, const __half* __restrict__ Bm,
    const float* __restrict__ bias, float* __restrict__ out,
    long ldout, int Nvalid)
{
    extern __shared__ __align__(16) __half smh[];
    const int mbase = blockIdx.y * 128;
    const int nbase = blockIdx.x * BN;
    MmaCtx<BN> cx;
    mma_mainloop<BN, KCH>(cx, A + (size_t)mbase * KLEN_,
                          Bm + (size_t)nbase * KLEN_, smh);

#pragma unroll
    for (int fm = 0; fm < 4; fm++) {
        int m0 = mbase + cx.wm * 64 + fm * 16 + (cx.l >> 2);
#pragma unroll
        for (int fn = 0; fn < MmaCtx<BN>::FN; fn++) {
            int n0 = nbase + cx.wn * (BN / 4) + fn * 8 + (cx.l & 3) * 2;
            if (n0 < Nvalid) {
                float b0 = bias ? bias[n0] : 0.f;
                float b1 = bias ? bias[n0 + 1] : 0.f;
                float2 v0 = make_float2(cx.d[fm][fn][0] + b0, cx.d[fm][fn][1] + b1);
                float2 v1 = make_float2(cx.d[fm][fn][2] + b0, cx.d[fm][fn][3] + b1);
                *(float2*)&out[(size_t)m0 * ldout + n0] = v0;
                *(float2*)&out[(size_t)(m0 + 8) * ldout + n0] = v1;
            }
        }
    }
}

// ---------------------------------------------------------------------------
// gemm2 + LSTM pointwise fused (BN=32, KCH=128). grid(64).
// ---------------------------------------------------------------------------
__global__ void __launch_bounds__(256) gemm2_lstm(int t) {
    extern __shared__ __align__(16) __half smh[];
    const int nbase = blockIdx.x * 32;
    MmaCtx<32> cx;
    mma_mainloop<32, 128>(cx, g_ctxH, g_W2H + (size_t)nbase * KLEN_, smh);

    __syncthreads();                        // pipeline smem -> gates smem reuse
    float* gsm = reinterpret_cast<float*>(smh);   // [128][33]
#pragma unroll
    for (int fm = 0; fm < 4; fm++) {
        int m0 = cx.wm * 64 + fm * 16 + (cx.l >> 2);
        int n0 = cx.wn * 8 + (cx.l & 3) * 2;
#pragma unroll
        for (int hh = 0; hh < 2; hh++) {
            int m = m0 + hh * 8;
            const float* pre =
                &g_gates_pre[((size_t)(t * B_ + m)) * 2048 + nbase + n0];
            const float* bh = &g_big1[m * 2560 + 512 + nbase + n0];
            gsm[m * 33 + n0]     = cx.d[fm][0][hh * 2]     + bh[0] + pre[0];
            gsm[m * 33 + n0 + 1] = cx.d[fm][0][hh * 2 + 1] + bh[1] + pre[1];
        }
    }
    __syncthreads();

    const int tid = threadIdx.x;
#pragma unroll
    for (int q = 0; q < 4; q++) {
        int idx = tid + q * 256;
        int b = idx >> 3, ul = idx & 7;     // 128 b x 8 units
        int u = (nbase >> 2) + ul;
        float gi = gsm[b * 33 + ul * 4 + 0];
        float gf = gsm[b * 33 + ul * 4 + 1];
        float gg = gsm[b * 33 + ul * 4 + 2];
        float go = gsm[b * 33 + ul * 4 + 3];
        float cn = fsig(gf) * g_c[(size_t)(t & 1) * (B_ * H_) + b * H_ + u]
                 + fsig(gi) * ftanh(gg);
        g_c[(size_t)((t + 1) & 1) * (B_ * H_) + b * H_ + u] = cn;
        float h = fsig(go) * ftanh(cn);
        g_hbig[(size_t)(t + 1) * (B_ * 512) + b * 512 + u] = __float2half_rn(h);
    }
}

// ---------------------------------------------------------------------------
// Attention: hp from big1[:, 0:512]; scores; softmax; ctx -> ctxH fp16.
// ---------------------------------------------------------------------------
__global__ void __launch_bounds__(512) attn_kernel(
    const float* __restrict__ enc, const float* __restrict__ vattn) {
    const int b = blockIdx.x, tid = threadIdx.x;
    __shared__ float hp_s[H_];
    __shared__ float v_s[H_];
    __shared__ float sc[64];

    hp_s[tid] = g_big1[b * 2560 + tid];
    v_s[tid] = vattn[tid];
    __syncthreads();

    const int w = tid >> 5, lane = tid & 31;
    const float* ep = g_enc_proj + (size_t)b * L_ * H_;
    for (int l = w; l < L_; l += 16) {
        const float* row = ep + l * H_;
        float p = 0.f;
#pragma unroll
        for (int k = lane; k < H_; k += 32)
            p += ftanh_hw(hp_s[k] + row[k]) * v_s[k];
#pragma unroll
        for (int o = 16; o; o >>= 1) p += __shfl_xor_sync(0xffffffffu, p, o);
        if (lane == 0) sc[l] = p;
    }
    __syncthreads();

    if (tid < 32) {
        float v0 = sc[tid];
        float v1 = (tid < L_ - 32) ? sc[32 + tid] : -1e30f;
        float mx = fmaxf(v0, v1);
#pragma unroll
        for (int o = 16; o; o >>= 1) mx = fmaxf(mx, __shfl_xor_sync(0xffffffffu, mx, o));
        float e0 = fex2((v0 - mx) * 1.4426950408889634f);
        float e1 = (tid < L_ - 32) ? fex2((v1 - mx) * 1.4426950408889634f) : 0.f;
        float s = e0 + e1;
#pragma unroll
        for (int o = 16; o; o >>= 1) s += __shfl_xor_sync(0xffffffffu, s, o);
        float r = frcp(s);
        sc[tid] = e0 * r;
        if (tid < L_ - 32) sc[32 + tid] = e1 * r;
    }
    __syncthreads();

    const float* eb = enc + (size_t)b * L_ * ENC_;
    float a = 0.f;
#pragma unroll 7
    for (int l = 0; l < L_; l++) a += sc[l] * eb[l * ENC_ + tid];
    g_ctxH[b * 512 + tid] = __float2half_rn(a);
}

// ---------------------------------------------------------------------------
// preamble kernels (fp16 converts)
// ---------------------------------------------------------------------------
__global__ void bias_sum_perm(const float* __restrict__ bi,
                              const float* __restrict__ bh) {
    int n = blockIdx.x * 256 + threadIdx.x;
    int o = ((n & 3) << 9) | (n >> 2);
    g_bsum[n] = bi[o] + bh[o];
}

__global__ void wfc_conv(const float* __restrict__ W_fc) {
    int n = blockIdx.x, j = threadIdx.x;
    float w = (n < V_) ? W_fc[(size_t)n * H_ + j] : 0.f;
    g_Wbig[(size_t)n * 512 + j] = __float2half_rn(w);
}

__global__ void w1h_conv(const float* __restrict__ W_h,
                         const float* __restrict__ W_hh) {
    int n = blockIdx.x, j = threadIdx.x;
    float w;
    if (n < 512) w = W_h[(size_t)n * H_ + j];
    else {
        int p = n - 512;
        int o = ((p & 3) << 9) | (p >> 2);
        w = W_hh[(size_t)o * H_ + j];
    }
    g_W1H[(size_t)n * 512 + j] = __float2half_rn(w);
}

__global__ void w2_conv(const float* __restrict__ W_ih) {
    int n = blockIdx.x, j = threadIdx.x;
    int o = ((n & 3) << 9) | (n >> 2);
    g_W2H[(size_t)n * 512 + j] = __float2half_rn(W_ih[(size_t)o * 1024 + 512 + j]);
}

__global__ void wih_emb_conv(const float* __restrict__ W_ih) {
    int n = blockIdx.x, j = threadIdx.x;
    int o = ((n & 3) << 9) | (n >> 2);
    g_WihB[(size_t)n * 512 + j] = __float2half_rn(W_ih[(size_t)o * 1024 + j]);
}

__global__ void h16_conv(const float* __restrict__ src, __half* __restrict__ dst) {
    int m = blockIdx.x, j = threadIdx.x;
    dst[(size_t)m * 512 + j] = __float2half_rn(src[(size_t)m * 512 + j]);
}

__global__ void emb_gather(const int* __restrict__ cap, const float* __restrict__ emb) {
    int m = blockIdx.x;
    int b = m & 127, t = m >> 7;
    int w = cap[b * T_ + t];
    int j = threadIdx.x;
    g_embX[(size_t)m * 512 + j] = __float2half_rn(emb[(size_t)w * E_ + j]);
}

__global__ void zero_state() {
    int i = blockIdx.x * 256 + threadIdx.x;   // 65536
    g_hbig[i] = __float2half_rn(0.f);         // slot 0 = h(0) = 0
    g_c[i] = 0.f;                             // parity 0
}

// ---------------------------------------------------------------------------
extern "C" void kernel_launch(void* const* d_in, const int* in_sizes, int n_in,
                              void* d_out, int out_size) {
    const int*   captions = (const int*)d_in[0];
    const float* enc      = (const float*)d_in[1];
    const float* emb      = (const float*)d_in[2];
    const float* W_h      = (const float*)d_in[3];
    const float* W_e      = (const float*)d_in[4];
    const float* v_attn   = (const float*)d_in[5];
    const float* W_ih     = (const float*)d_in[6];
    const float* W_hh     = (const float*)d_in[7];
    const float* b_ih     = (const float*)d_in[8];
    const float* b_hh     = (const float*)d_in[9];
    const float* W_fc     = (const float*)d_in[10];
    const float* b_fc     = (const float*)d_in[11];
    float* out = (float*)d_out;

    static cudaStream_t s2 = nullptr, s3 = nullptr, s4 = nullptr;
    static cudaEvent_t evStart = nullptr, evG0 = nullptr, evG1 = nullptr,
                       evH = nullptr, evW = nullptr, evJ2 = nullptr,
                       evJ4 = nullptr;
    if (!s2) {
        cudaStreamCreateWithFlags(&s2, cudaStreamNonBlocking);
        cudaStreamCreateWithFlags(&s3, cudaStreamNonBlocking);
        cudaStreamCreateWithFlags(&s4, cudaStreamNonBlocking);
        cudaEventCreateWithFlags(&evStart, cudaEventDisableTiming);
        cudaEventCreateWithFlags(&evG0, cudaEventDisableTiming);
        cudaEventCreateWithFlags(&evG1, cudaEventDisableTiming);
        cudaEventCreateWithFlags(&evH,  cudaEventDisableTiming);
        cudaEventCreateWithFlags(&evW,  cudaEventDisableTiming);
        cudaEventCreateWithFlags(&evJ2, cudaEventDisableTiming);
        cudaEventCreateWithFlags(&evJ4, cudaEventDisableTiming);
    }
    cudaFuncSetAttribute((const void*)mma_gemm<128, 64>,
                         cudaFuncAttributeMaxDynamicSharedMemorySize, SMEM128_);
    cudaFuncSetAttribute((const void*)mma_gemm<32, 128>,
                         cudaFuncAttributeMaxDynamicSharedMemorySize, SMEM32_);
    cudaFuncSetAttribute((const void*)gemm2_lstm,
                         cudaFuncAttributeMaxDynamicSharedMemorySize, SMEM32_);

    float *enc_proj, *gates_pre, *bsum;
    __half *Wbig, *hbig, *W1H, *encA, *embX, *WeB, *WihB;
    cudaGetSymbolAddress((void**)&enc_proj,  g_enc_proj);
    cudaGetSymbolAddress((void**)&gates_pre, g_gates_pre);
    cudaGetSymbolAddress((void**)&bsum,      g_bsum);
    cudaGetSymbolAddress((void**)&Wbig,      g_Wbig);
    cudaGetSymbolAddress((void**)&hbig,      g_hbig);
    cudaGetSymbolAddress((void**)&W1H,       g_W1H);
    cudaGetSymbolAddress((void**)&encA,      g_encA);
    cudaGetSymbolAddress((void**)&embX,      g_embX);
    cudaGetSymbolAddress((void**)&WeB,       g_WeB);
    cudaGetSymbolAddress((void**)&WihB,      g_WihB);
    float* big1; cudaGetSymbolAddress((void**)&big1, g_big1);

    // fork: all side streams join the capture BEFORE any of their work
    zero_state<<<256, 256>>>();
    cudaEventRecord(evStart, 0);
    cudaStreamWaitEvent(s2, evStart, 0);
    cudaStreamWaitEvent(s3, evStart, 0);
    cudaStreamWaitEvent(s4, evStart, 0);

    // s2: W_fc fp16 (feeds logits on both logits streams)
    wfc_conv<<<VPAD_, 512, 0, s2>>>(W_fc);
    cudaEventRecord(evW, s2);
    cudaStreamWaitEvent(s4, evW, 0);

    // s3: gates_pre pipeline, split t<4 / t>=4
    bias_sum_perm<<<8, 256, 0, s3>>>(b_ih, b_hh);
    emb_gather<<<BT_, 512, 0, s3>>>(captions, emb);
    wih_emb_conv<<<4 * H_, 512, 0, s3>>>(W_ih);
    mma_gemm<128, 64><<<dim3(16, 4), 256, SMEM128_, s3>>>(
        embX, WihB, bsum, gates_pre, 4L * H_, 4 * H_);
    cudaEventRecord(evG0, s3);
    mma_gemm<128, 64><<<dim3(16, 21), 256, SMEM128_, s3>>>(
        embX + (size_t)512 * 512, WihB, bsum,
        gates_pre + 512L * 2048, 4L * H_, 4 * H_);
    cudaEventRecord(evG1, s3);

    // s1: chain weights + enc_proj
    w1h_conv<<<2560, 512>>>(W_h, W_hh);
    w2_conv<<<2048, 512>>>(W_ih);
    h16_conv<<<H_, 512>>>(W_e, WeB);
    h16_conv<<<BL_, 512>>>(enc, encA);
    mma_gemm<128, 64><<<dim3(4, BL_ / 128), 256, SMEM128_>>>(
        encA, WeB, nullptr, enc_proj, (long)H_, H_);

    cudaStream_t sL[2] = {s2, s4};
    for (int t = 0; t < T_; t++) {
        // gemm1: big1 = h(t) @ [W_h | perm(W_hh)]^T  (BN=32, KCH=128, 80 CTAs)
        mma_gemm<32, 128><<<dim3(80, 1), 256, SMEM32_>>>(
            hbig + (size_t)t * B_ * 512, W1H, nullptr, big1, 2560L, 2560);
        attn_kernel<<<B_, 512>>>(enc, v_attn);
        if (t == 0) cudaStreamWaitEvent(0, evG0, 0);
        if (t == 4) cudaStreamWaitEvent(0, evG1, 0);
        gemm2_lstm<<<dim3(64, 1), 256, SMEM32_>>>(t);
        cudaEventRecord(evH, 0);
        cudaStreamWaitEvent(sL[t & 1], evH, 0);
        // logits: single-term fp16, K=512, 79 CTAs, alternating streams
        mma_gemm<128, 64><<<dim3(79, 1), 256, SMEM128_, sL[t & 1]>>>(
            hbig + (size_t)(t + 1) * B_ * 512, Wbig, b_fc,
            out + (size_t)t * V_, (long)(T_ * V_), V_);
    }
    cudaEventRecord(evJ2, s2);
    cudaStreamWaitEvent(0, evJ2, 0);
    cudaEventRecord(evJ4, s4);
    cudaStreamWaitEvent(0, evJ4, 0);
}